// round 12
// baseline (speedup 1.0000x reference)
#include <cuda_runtime.h>
#include <cuda_fp16.h>
#include <cstdint>

// ---------------------------------------------------------------------------
//   x: [512,512]  z: [512,256]
//   Wq: [256,32768]  Wk/Wv: [512,32768]  Wo: [32768,512]
// ---------------------------------------------------------------------------
#define TOK   512
#define DTOT  32768
#define NSPLIT 32

typedef unsigned long long ull;

__device__ __half g_Qh[TOK * (size_t)DTOT];
__device__ __half g_Kh[TOK * (size_t)DTOT];
__device__ __half g_Vh[TOK * (size_t)DTOT];
__device__ __half g_AOh[TOK * (size_t)DTOT];
__device__ float  g_part[NSPLIT * 512 * 512];
__device__ __half g_xh[512 * 512];
__device__ __half g_zh[512 * 256];
__device__ __half g_Wqh[256 * (size_t)DTOT];
__device__ __half g_Wkh[512 * (size_t)DTOT];
__device__ __half g_Wvh[512 * (size_t)DTOT];
__device__ __half g_Woh[(size_t)DTOT * 512];

// ---------------------------------------------------------------------------
// helpers
// ---------------------------------------------------------------------------
__device__ __forceinline__ uint32_t smem_u32(const void* p) {
    uint32_t a;
    asm("{ .reg .u64 t; cvta.to.shared.u64 t, %1; cvt.u32.u64 %0, t; }" : "=r"(a) : "l"(p));
    return a;
}
__device__ __forceinline__ void ldm4(uint32_t r[4], uint32_t addr) {
    asm volatile("ldmatrix.sync.aligned.m8n8.x4.shared.b16 {%0,%1,%2,%3}, [%4];"
                 : "=r"(r[0]), "=r"(r[1]), "=r"(r[2]), "=r"(r[3]) : "r"(addr));
}
__device__ __forceinline__ void ldm4t(uint32_t r[4], uint32_t addr) {
    asm volatile("ldmatrix.sync.aligned.m8n8.x4.trans.shared.b16 {%0,%1,%2,%3}, [%4];"
                 : "=r"(r[0]), "=r"(r[1]), "=r"(r[2]), "=r"(r[3]) : "r"(addr));
}
__device__ __forceinline__ void mma16816(float c[4], const uint32_t a[4], const uint32_t b[2]) {
    asm volatile(
        "mma.sync.aligned.m16n8k16.row.col.f32.f16.f16.f32 "
        "{%0,%1,%2,%3}, {%4,%5,%6,%7}, {%8,%9}, {%0,%1,%2,%3};"
        : "+f"(c[0]), "+f"(c[1]), "+f"(c[2]), "+f"(c[3])
        : "r"(a[0]), "r"(a[1]), "r"(a[2]), "r"(a[3]), "r"(b[0]), "r"(b[1]));
}
__device__ __forceinline__ uint32_t pack2(float e0, float e1) {   // lo=e0, hi=e1
    uint32_t r;
    asm("cvt.rn.f16x2.f32 %0, %1, %2;" : "=r"(r) : "f"(e1), "f"(e0));
    return r;
}
#define CPA16(sm, gm)  asm volatile("cp.async.cg.shared.global [%0], [%1], 16;" :: "r"(sm), "l"(gm))
#define CPA16L1(sm, gm) asm volatile("cp.async.ca.shared.global [%0], [%1], 16;" :: "r"(sm), "l"(gm))
#define CPA_COMMIT()   asm volatile("cp.async.commit_group;" ::: "memory")
#define CPA_WAIT1()    asm volatile("cp.async.wait_group 1;" ::: "memory")
#define CPA_WAIT0()    asm volatile("cp.async.wait_group 0;" ::: "memory")

// ---------------------------------------------------------------------------
// fp32 -> fp16 round
// ---------------------------------------------------------------------------
__global__ void conv_round_kernel(const float4* __restrict__ src,
                                  uint2* __restrict__ dst, int n4)
{
    int i = blockIdx.x * 256 + threadIdx.x;
    if (i >= n4) return;
    float4 v = src[i];
    uint2 o;
    o.x = pack2(v.x, v.y);
    o.y = pack2(v.z, v.w);
    dst[i] = o;
}

// ---------------------------------------------------------------------------
// GEMM C = A @ B (+bias): A fp16, B fp16.
// 512 threads, block tile 128x256, BK=64; warp tile 32x64 (4x4 warp grid).
// 3-stage cp.async pipeline; B-fragment double buffering in the ks loop.
// mode: 0 = fp32 C; 2 = fp16 C   (+bias if non-null)
// ---------------------------------------------------------------------------
#define LDA_S 72
#define LDB_S 264
#define ASTG  18432
#define BSTG  33792
#define BOFF  (3 * ASTG)
#define GSMEM (BOFF + 3 * BSTG)     // 156672

__global__ __launch_bounds__(512)
void gemm_mma6_kernel(const __half* __restrict__ Ahg, int lda,
                      const __half* __restrict__ Bhg, int ldb,
                      const float* __restrict__ bias, int mode,
                      float* __restrict__ Cf, __half* __restrict__ Ch, int ldc,
                      size_t csplit, int ksize)
{
    extern __shared__ __align__(16) char dsm[];
    const int tid = threadIdx.x, lane = tid & 31, wid = tid >> 5;
    const int wm = wid & 3, wn = wid >> 2;
    const int n0 = blockIdx.x << 8, m0 = blockIdx.y << 7;
    const int kbeg = blockIdx.z * ksize;
    if (Cf) Cf += (size_t)blockIdx.z * csplit;

    const uint32_t smb = smem_u32(dsm);

    float acc[2][8][4];
#pragma unroll
    for (int i = 0; i < 2; i++)
#pragma unroll
        for (int j = 0; j < 8; j++)
#pragma unroll
            for (int k = 0; k < 4; k++) acc[i][j][k] = 0.f;

    const int lr = lane & 15, lc = lane >> 4;

    const int a_r = tid >> 3, a_c = (tid & 7) << 3;
    const int b_r = tid >> 5, b_c = (tid & 31) << 3;

    const __half* Aph = Ahg + (size_t)(m0 + a_r) * lda + kbeg + a_c;
    const __half* Bp  = Bhg + (size_t)(kbeg + b_r) * ldb + n0 + b_c;

    const uint32_t a_dst0 = smb + a_r * (2 * LDA_S) + 2 * a_c;
    const uint32_t a_dst1 = smb + (a_r + 64) * (2 * LDA_S) + 2 * a_c;
    const uint32_t b_dst  = smb + BOFF + b_r * (2 * LDB_S) + 2 * b_c;

#define ISSUE(ch, s) do { \
    CPA16(a_dst0 + (s) * ASTG, Aph + (ch) * 64); \
    CPA16(a_dst1 + (s) * ASTG, Aph + (size_t)64 * lda + (ch) * 64); \
    _Pragma("unroll") \
    for (int p = 0; p < 4; p++) \
        CPA16(b_dst + (s) * BSTG + p * 16 * (2 * LDB_S), \
              Bp + (size_t)((ch) * 64 + p * 16) * ldb); } while (0)

    const int nch = ksize >> 6;
    ISSUE(0, 0); CPA_COMMIT();
    if (nch > 1) { ISSUE(1, 1); CPA_COMMIT(); }
    else CPA_COMMIT();
    CPA_WAIT1();
    __syncthreads();

    for (int ch = 0; ch < nch; ch++) {
        const int cur = ch % 3;
        if (ch + 2 < nch) ISSUE(ch + 2, (ch + 2) % 3);
        CPA_COMMIT();

        const uint32_t ahb = smb + cur * ASTG;
        const uint32_t bhb = smb + BOFF + cur * BSTG;

#pragma unroll
        for (int ks = 0; ks < 4; ks++) {
            uint32_t a_f[2][4];
#pragma unroll
            for (int mf = 0; mf < 2; mf++) {
                uint32_t adr = 2 * ((wm * 32 + mf * 16 + lr) * LDA_S + ks * 16 + lc * 8);
                ldm4(a_f[mf], ahb + adr);
            }
            // B-fragment double buffer: prefetch nb+1 before nb's MMAs
            uint32_t b0[4], b1[4];
            {
                uint32_t adr = 2 * ((ks * 16 + lr) * LDB_S + wn * 64 + lc * 8);
                ldm4t(b0, bhb + adr);
            }
#pragma unroll
            for (int nb = 0; nb < 4; nb++) {
                uint32_t* bc = (nb & 1) ? b1 : b0;
                uint32_t* bn = (nb & 1) ? b0 : b1;
                if (nb < 3) {
                    uint32_t adr = 2 * ((ks * 16 + lr) * LDB_S + wn * 64 + (nb + 1) * 16 + lc * 8);
                    ldm4t(bn, bhb + adr);
                }
#pragma unroll
                for (int mf = 0; mf < 2; mf++)
#pragma unroll
                    for (int hf = 0; hf < 2; hf++) {
                        uint32_t bb[2] = {bc[hf * 2], bc[hf * 2 + 1]};
                        mma16816(acc[mf][nb * 2 + hf], a_f[mf], bb);
                    }
            }
        }
        CPA_WAIT1();
        __syncthreads();
    }
#undef ISSUE

    const int rbase = m0 + wm * 32 + (lane >> 2);
    const int cb = n0 + wn * 64 + (lane & 3) * 2;
#pragma unroll
    for (int mf = 0; mf < 2; mf++)
#pragma unroll
        for (int nf = 0; nf < 8; nf++) {
            int rr = rbase + mf * 16;
            int cc = cb + nf * 8;
            float2 v0 = make_float2(acc[mf][nf][0], acc[mf][nf][1]);
            float2 v1 = make_float2(acc[mf][nf][2], acc[mf][nf][3]);
            if (bias) {
                float2 bb = *(const float2*)(bias + cc);
                v0.x += bb.x; v0.y += bb.y;
                v1.x += bb.x; v1.y += bb.y;
            }
            if (mode == 0) {
                *(float2*)(Cf + (size_t)rr * ldc + cc) = v0;
                *(float2*)(Cf + (size_t)(rr + 8) * ldc + cc) = v1;
            } else {
                *(uint32_t*)(Ch + (size_t)rr * ldc + cc) = pack2(v0.x, v0.y);
                *(uint32_t*)(Ch + (size_t)(rr + 8) * ldc + cc) = pack2(v1.x, v1.y);
            }
        }
}

// ---------------------------------------------------------------------------
// Tensor-core attention: Q, K, V fp16 in; AO fp16 out. cp.async tile fills.
// One head (64x64) per 128-thread block; warp w owns q-rows 16w..16w+15.
// ---------------------------------------------------------------------------
#define ALD 72

__global__ __launch_bounds__(128)
void attn_mma_kernel(const __half* __restrict__ Qhg, const __half* __restrict__ Khg,
                     const __half* __restrict__ Vhg, __half* __restrict__ AOh)
{
    __shared__ __align__(16) __half QH[64 * ALD];
    __shared__ __align__(16) __half KH[64 * ALD];
    __shared__ __align__(16) __half VH[64 * ALD];

    const int tid = threadIdx.x, lane = tid & 31, w = tid >> 5;
    const size_t base = (size_t)blockIdx.x * 4096;

    const uint32_t qh = smem_u32(QH), kh = smem_u32(KH), vh = smem_u32(VH);

    // async tile fills: 512 chunks of 16B per array, 4 per thread per array
#pragma unroll
    for (int i = 0; i < 4; i++) {
        int f = i * 128 + tid;             // 0..511
        int r = f >> 3, c = (f & 7) << 3;
        uint32_t off = 2 * (r * ALD + c);
        size_t g = base + r * 64 + c;
        CPA16L1(qh + off, Qhg + g);
        CPA16L1(kh + off, Khg + g);
        CPA16L1(vh + off, Vhg + g);
    }
    CPA_COMMIT();
    CPA_WAIT0();
    __syncthreads();

    const int lr = lane & 15, lc = lane >> 4;

    float S[8][4];
#pragma unroll
    for (int i = 0; i < 8; i++)
#pragma unroll
        for (int j = 0; j < 4; j++) S[i][j] = 0.f;

#pragma unroll
    for (int ks = 0; ks < 4; ks++) {
        uint32_t a_f[4];
        uint32_t adr = 2 * ((w * 16 + lr) * ALD + ks * 16 + lc * 8);
        ldm4(a_f, qh + adr);
#pragma unroll
        for (int nb = 0; nb < 4; nb++) {
            uint32_t badr = 2 * ((nb * 16 + (lane & 7) + (lane >> 4) * 8) * ALD
                                 + ks * 16 + ((lane >> 3) & 1) * 8);
            uint32_t b_h[4];
            ldm4(b_h, kh + badr);
#pragma unroll
            for (int hf = 0; hf < 2; hf++) {
                uint32_t bb[2] = {b_h[hf * 2], b_h[hf * 2 + 1]};
                mma16816(S[nb * 2 + hf], a_f, bb);
            }
        }
    }

    float mlo = -1e30f, mhi = -1e30f;
#pragma unroll
    for (int nf = 0; nf < 8; nf++) {
        S[nf][0] *= 0.125f; S[nf][1] *= 0.125f;
        S[nf][2] *= 0.125f; S[nf][3] *= 0.125f;
        mlo = fmaxf(mlo, fmaxf(S[nf][0], S[nf][1]));
        mhi = fmaxf(mhi, fmaxf(S[nf][2], S[nf][3]));
    }
    mlo = fmaxf(mlo, __shfl_xor_sync(0xffffffffu, mlo, 1));
    mlo = fmaxf(mlo, __shfl_xor_sync(0xffffffffu, mlo, 2));
    mhi = fmaxf(mhi, __shfl_xor_sync(0xffffffffu, mhi, 1));
    mhi = fmaxf(mhi, __shfl_xor_sync(0xffffffffu, mhi, 2));

    float slo = 0.f, shi = 0.f;
#pragma unroll
    for (int nf = 0; nf < 8; nf++) {
        S[nf][0] = __expf(S[nf][0] - mlo); slo += S[nf][0];
        S[nf][1] = __expf(S[nf][1] - mlo); slo += S[nf][1];
        S[nf][2] = __expf(S[nf][2] - mhi); shi += S[nf][2];
        S[nf][3] = __expf(S[nf][3] - mhi); shi += S[nf][3];
    }
    slo += __shfl_xor_sync(0xffffffffu, slo, 1);
    slo += __shfl_xor_sync(0xffffffffu, slo, 2);
    shi += __shfl_xor_sync(0xffffffffu, shi, 1);
    shi += __shfl_xor_sync(0xffffffffu, shi, 2);
    const float ilo = 1.f / slo, ihi = 1.f / shi;
#pragma unroll
    for (int nf = 0; nf < 8; nf++) {
        S[nf][0] *= ilo; S[nf][1] *= ilo;
        S[nf][2] *= ihi; S[nf][3] *= ihi;
    }

    uint32_t p_h[4][4];
#pragma unroll
    for (int j = 0; j < 4; j++) {
#pragma unroll
        for (int q = 0; q < 2; q++) {
            const float* s = (q == 0) ? S[2 * j] : S[2 * j + 1];
            p_h[j][q * 2 + 0] = pack2(s[0], s[1]);
            p_h[j][q * 2 + 1] = pack2(s[2], s[3]);
        }
    }

    float O[8][4];
#pragma unroll
    for (int i = 0; i < 8; i++)
#pragma unroll
        for (int j = 0; j < 4; j++) O[i][j] = 0.f;

#pragma unroll
    for (int j = 0; j < 4; j++) {
#pragma unroll
        for (int nb = 0; nb < 4; nb++) {
            uint32_t badr = 2 * ((j * 16 + lr) * ALD + nb * 16 + lc * 8);
            uint32_t b_h[4];
            ldm4t(b_h, vh + badr);
#pragma unroll
            for (int hf = 0; hf < 2; hf++) {
                uint32_t bb[2] = {b_h[hf * 2], b_h[hf * 2 + 1]};
                mma16816(O[nb * 2 + hf], p_h[j], bb);
            }
        }
    }

    const size_t ob = base + (size_t)(w * 16 + (lane >> 2)) * 64 + (lane & 3) * 2;
#pragma unroll
    for (int nf = 0; nf < 8; nf++) {
        *(uint32_t*)(AOh + ob + nf * 8)       = pack2(O[nf][0], O[nf][1]);
        *(uint32_t*)(AOh + ob + 512 + nf * 8) = pack2(O[nf][2], O[nf][3]);
    }
}

// ---------------------------------------------------------------------------
// Reduce NSPLIT split-K partials + bias -> out (512x512).
// ---------------------------------------------------------------------------
__global__ void reduce_out_kernel(const float4* __restrict__ part,
                                  const float4* __restrict__ bo4,
                                  float4* __restrict__ out)
{
    int i = blockIdx.x * 256 + threadIdx.x;     // 0..65535
    float4 s = bo4[i & 127];
#pragma unroll
    for (int p = 0; p < NSPLIT; p++) {
        float4 v = part[(size_t)p * 65536 + i];
        s.x += v.x; s.y += v.y; s.z += v.z; s.w += v.w;
    }
    out[i] = s;
}

// ---------------------------------------------------------------------------
extern "C" void kernel_launch(void* const* d_in, const int* in_sizes, int n_in,
                              void* d_out, int out_size)
{
    const float* x  = (const float*)d_in[0];
    const float* z  = (const float*)d_in[1];
    const float* Wq = (const float*)d_in[2];
    const float* bq = (const float*)d_in[3];
    const float* Wk = (const float*)d_in[4];
    const float* bk = (const float*)d_in[5];
    const float* Wv = (const float*)d_in[6];
    const float* bv = (const float*)d_in[7];
    const float* Wo = (const float*)d_in[8];
    const float* bo = (const float*)d_in[9];
    float* out = (float*)d_out;

    __half *Qh, *Kh, *Vh, *AOh, *xh, *zh;
    __half *Wqh, *Wkh, *Wvh, *Woh;
    float* Part;
    cudaGetSymbolAddress((void**)&Qh,  g_Qh);
    cudaGetSymbolAddress((void**)&Kh,  g_Kh);
    cudaGetSymbolAddress((void**)&Vh,  g_Vh);
    cudaGetSymbolAddress((void**)&AOh, g_AOh);
    cudaGetSymbolAddress((void**)&Part, g_part);
    cudaGetSymbolAddress((void**)&xh,  g_xh);
    cudaGetSymbolAddress((void**)&zh,  g_zh);
    cudaGetSymbolAddress((void**)&Wqh, g_Wqh);
    cudaGetSymbolAddress((void**)&Wkh, g_Wkh);
    cudaGetSymbolAddress((void**)&Wvh, g_Wvh);
    cudaGetSymbolAddress((void**)&Woh, g_Woh);

    static cudaStream_t s1 = nullptr, s2 = nullptr, s3 = nullptr;
    static cudaEvent_t ev0, evz, evx, evq, evk, evv;
    if (!s1) {
        cudaStreamCreateWithFlags(&s1, cudaStreamNonBlocking);
        cudaStreamCreateWithFlags(&s2, cudaStreamNonBlocking);
        cudaStreamCreateWithFlags(&s3, cudaStreamNonBlocking);
        cudaEventCreateWithFlags(&ev0, cudaEventDisableTiming);
        cudaEventCreateWithFlags(&evz, cudaEventDisableTiming);
        cudaEventCreateWithFlags(&evx, cudaEventDisableTiming);
        cudaEventCreateWithFlags(&evq, cudaEventDisableTiming);
        cudaEventCreateWithFlags(&evk, cudaEventDisableTiming);
        cudaEventCreateWithFlags(&evv, cudaEventDisableTiming);
        cudaFuncSetAttribute(gemm_mma6_kernel,
                             cudaFuncAttributeMaxDynamicSharedMemorySize, GSMEM);
    }

    // Fork side streams from the origin stream.
    cudaEventRecord(ev0, 0);
    cudaStreamWaitEvent(s1, ev0, 0);
    cudaStreamWaitEvent(s2, ev0, 0);
    cudaStreamWaitEvent(s3, ev0, 0);

    // s0: activation rounding (+Wo rounding, overlapped by side streams)
    conv_round_kernel<<<128, 256>>>((const float4*)z, (uint2*)zh, 32768);
    cudaEventRecord(evz, 0);
    conv_round_kernel<<<256, 256>>>((const float4*)x, (uint2*)xh, 65536);
    cudaEventRecord(evx, 0);
    conv_round_kernel<<<16384, 256>>>((const float4*)Wo, (uint2*)Woh, 4194304);

    dim3 gQKV(DTOT / 256, TOK / 128, 1);

    // s1: Wq conversion + Q projection (fp16)
    conv_round_kernel<<<8192, 256, 0, s1>>>((const float4*)Wq, (uint2*)Wqh, 2097152);
    cudaStreamWaitEvent(s1, evz, 0);
    gemm_mma6_kernel<<<gQKV, 512, GSMEM, s1>>>(zh, 256, Wqh, DTOT, bq, 2,
                                               nullptr, Qh, DTOT, 0, 256);
    cudaEventRecord(evq, s1);

    // s2: Wk conversion + K projection
    conv_round_kernel<<<16384, 256, 0, s2>>>((const float4*)Wk, (uint2*)Wkh, 4194304);
    cudaStreamWaitEvent(s2, evx, 0);
    gemm_mma6_kernel<<<gQKV, 512, GSMEM, s2>>>(xh, 512, Wkh, DTOT, bk, 2,
                                               nullptr, Kh, DTOT, 0, 512);
    cudaEventRecord(evk, s2);

    // s3: Wv conversion + V projection
    conv_round_kernel<<<16384, 256, 0, s3>>>((const float4*)Wv, (uint2*)Wvh, 4194304);
    cudaStreamWaitEvent(s3, evx, 0);
    gemm_mma6_kernel<<<gQKV, 512, GSMEM, s3>>>(xh, 512, Wvh, DTOT, bv, 2,
                                               nullptr, Vh, DTOT, 0, 512);
    cudaEventRecord(evv, s3);

    // join back to s0
    cudaStreamWaitEvent(0, evq, 0);
    cudaStreamWaitEvent(0, evk, 0);
    cudaStreamWaitEvent(0, evv, 0);

    // Attention: 4096 heads; writes AO fp16
    attn_mma_kernel<<<4096, 128>>>(Qh, Kh, Vh, AOh);

    // Output projection: split-K partials then reduce (+bias)
    dim3 gO(512 / 256, 512 / 128, NSPLIT);
    gemm_mma6_kernel<<<gO, 512, GSMEM>>>(AOh, DTOT, Woh, 512, nullptr, 0,
                                         Part, nullptr, 512,
                                         (size_t)512 * 512, DTOT / NSPLIT);

    reduce_out_kernel<<<256, 256>>>((const float4*)Part, (const float4*)bo,
                                    (float4*)out);
}

// round 13
// speedup vs baseline: 1.0097x; 1.0097x over previous
#include <cuda_runtime.h>
#include <cuda_fp16.h>
#include <cstdint>

// ---------------------------------------------------------------------------
//   x: [512,512]  z: [512,256]
//   Wq: [256,32768]  Wk/Wv: [512,32768]  Wo: [32768,512]
// ---------------------------------------------------------------------------
#define TOK   512
#define DTOT  32768
#define NSPLIT 16

typedef unsigned long long ull;

__device__ __half g_Qh[TOK * (size_t)DTOT];
__device__ __half g_Kh[TOK * (size_t)DTOT];
__device__ __half g_Vh[TOK * (size_t)DTOT];
__device__ __half g_AOh[TOK * (size_t)DTOT];
__device__ float  g_part[NSPLIT * 512 * 512];
__device__ __half g_xh[512 * 512];
__device__ __half g_zh[512 * 256];
__device__ __half g_Wqh[256 * (size_t)DTOT];
__device__ __half g_Wkh[512 * (size_t)DTOT];
__device__ __half g_Wvh[512 * (size_t)DTOT];
__device__ __half g_Woh[(size_t)DTOT * 512];

// ---------------------------------------------------------------------------
// helpers
// ---------------------------------------------------------------------------
__device__ __forceinline__ uint32_t smem_u32(const void* p) {
    uint32_t a;
    asm("{ .reg .u64 t; cvta.to.shared.u64 t, %1; cvt.u32.u64 %0, t; }" : "=r"(a) : "l"(p));
    return a;
}
__device__ __forceinline__ void ldm4(uint32_t r[4], uint32_t addr) {
    asm volatile("ldmatrix.sync.aligned.m8n8.x4.shared.b16 {%0,%1,%2,%3}, [%4];"
                 : "=r"(r[0]), "=r"(r[1]), "=r"(r[2]), "=r"(r[3]) : "r"(addr));
}
__device__ __forceinline__ void ldm4t(uint32_t r[4], uint32_t addr) {
    asm volatile("ldmatrix.sync.aligned.m8n8.x4.trans.shared.b16 {%0,%1,%2,%3}, [%4];"
                 : "=r"(r[0]), "=r"(r[1]), "=r"(r[2]), "=r"(r[3]) : "r"(addr));
}
__device__ __forceinline__ void mma16816(float c[4], const uint32_t a[4], const uint32_t b[2]) {
    asm volatile(
        "mma.sync.aligned.m16n8k16.row.col.f32.f16.f16.f32 "
        "{%0,%1,%2,%3}, {%4,%5,%6,%7}, {%8,%9}, {%0,%1,%2,%3};"
        : "+f"(c[0]), "+f"(c[1]), "+f"(c[2]), "+f"(c[3])
        : "r"(a[0]), "r"(a[1]), "r"(a[2]), "r"(a[3]), "r"(b[0]), "r"(b[1]));
}
__device__ __forceinline__ uint32_t pack2(float e0, float e1) {   // lo=e0, hi=e1
    uint32_t r;
    asm("cvt.rn.f16x2.f32 %0, %1, %2;" : "=r"(r) : "f"(e1), "f"(e0));
    return r;
}
#define CPA16(sm, gm) asm volatile("cp.async.ca.shared.global [%0], [%1], 16;" :: "r"(sm), "l"(gm))
#define CPA_COMMIT()  asm volatile("cp.async.commit_group;" ::: "memory")
#define CPA_WAIT1()   asm volatile("cp.async.wait_group 1;" ::: "memory")

// ---------------------------------------------------------------------------
// fp32 -> fp16 round
// ---------------------------------------------------------------------------
__global__ void conv_round_kernel(const float4* __restrict__ src,
                                  uint2* __restrict__ dst, int n4)
{
    int i = blockIdx.x * 256 + threadIdx.x;
    if (i >= n4) return;
    float4 v = src[i];
    uint2 o;
    o.x = pack2(v.x, v.y);
    o.y = pack2(v.z, v.w);
    dst[i] = o;
}

// ---------------------------------------------------------------------------
// GEMM C = A @ B (+bias): A fp16, B fp16.
// 256 threads, block tile 128x128, BK=64; warp tile 32x64 (4x2 warp grid).
// 3-stage cp.async pipeline; 2 CTAs/SM.
// smem/stage: A 128x72 halves = 18432 B | B 64x136 halves = 17408 B
// mode: 0 = fp32 C; 2 = fp16 C   (+bias if non-null)
// ---------------------------------------------------------------------------
#define LDA_S 72
#define LDB_S 136
#define ASTG  18432
#define BSTG  17408
#define BOFF  (3 * ASTG)
#define GSMEM (BOFF + 3 * BSTG)     // 107520

__global__ __launch_bounds__(256, 2)
void gemm_mma7_kernel(const __half* __restrict__ Ahg, int lda,
                      const __half* __restrict__ Bhg, int ldb,
                      const float* __restrict__ bias, int mode,
                      float* __restrict__ Cf, __half* __restrict__ Ch, int ldc,
                      size_t csplit, int ksize)
{
    extern __shared__ __align__(16) char dsm[];
    const int tid = threadIdx.x, lane = tid & 31, wid = tid >> 5;
    const int wm = wid & 3, wn = wid >> 2;        // 4 x 2 warp grid
    const int n0 = blockIdx.x << 7, m0 = blockIdx.y << 7;
    const int kbeg = blockIdx.z * ksize;
    if (Cf) Cf += (size_t)blockIdx.z * csplit;

    const uint32_t smb = smem_u32(dsm);

    float acc[2][8][4];
#pragma unroll
    for (int i = 0; i < 2; i++)
#pragma unroll
        for (int j = 0; j < 8; j++)
#pragma unroll
            for (int k = 0; k < 4; k++) acc[i][j][k] = 0.f;

    const int lr = lane & 15, lc = lane >> 4;

    // A: 128 rows x 64 halves -> 1024 chunks of 16B; 4 per thread (rows +32p)
    const int a_r = tid >> 3, a_c = (tid & 7) << 3;
    // B: 64 rows x 128 halves -> 1024 chunks; 4 per thread (rows +16p)
    const int b_r = tid >> 4, b_c = (tid & 15) << 3;

    const __half* Aph = Ahg + (size_t)(m0 + a_r) * lda + kbeg + a_c;
    const __half* Bp  = Bhg + (size_t)(kbeg + b_r) * ldb + n0 + b_c;

    const uint32_t a_dst = smb + a_r * (2 * LDA_S) + 2 * a_c;
    const uint32_t b_dst = smb + BOFF + b_r * (2 * LDB_S) + 2 * b_c;

#define ISSUE(ch, s) do { \
    _Pragma("unroll") \
    for (int p = 0; p < 4; p++) \
        CPA16(a_dst + (s) * ASTG + p * 32 * (2 * LDA_S), \
              Aph + (size_t)(p * 32) * lda + (ch) * 64); \
    _Pragma("unroll") \
    for (int p = 0; p < 4; p++) \
        CPA16(b_dst + (s) * BSTG + p * 16 * (2 * LDB_S), \
              Bp + (size_t)((ch) * 64 + p * 16) * ldb); } while (0)

    const int nch = ksize >> 6;
    ISSUE(0, 0); CPA_COMMIT();
    if (nch > 1) { ISSUE(1, 1); CPA_COMMIT(); }
    else CPA_COMMIT();
    CPA_WAIT1();
    __syncthreads();

    for (int ch = 0; ch < nch; ch++) {
        const int cur = ch % 3;
        if (ch + 2 < nch) ISSUE(ch + 2, (ch + 2) % 3);
        CPA_COMMIT();

        const uint32_t ahb = smb + cur * ASTG;
        const uint32_t bhb = smb + BOFF + cur * BSTG;

#pragma unroll
        for (int ks = 0; ks < 4; ks++) {
            uint32_t a_f[2][4];
#pragma unroll
            for (int mf = 0; mf < 2; mf++) {
                uint32_t adr = 2 * ((wm * 32 + mf * 16 + lr) * LDA_S + ks * 16 + lc * 8);
                ldm4(a_f[mf], ahb + adr);
            }
#pragma unroll
            for (int nb = 0; nb < 4; nb++) {
                uint32_t b_f[4];
                uint32_t adr = 2 * ((ks * 16 + lr) * LDB_S + wn * 64 + nb * 16 + lc * 8);
                ldm4t(b_f, bhb + adr);
#pragma unroll
                for (int mf = 0; mf < 2; mf++)
#pragma unroll
                    for (int hf = 0; hf < 2; hf++) {
                        uint32_t bb[2] = {b_f[hf * 2], b_f[hf * 2 + 1]};
                        mma16816(acc[mf][nb * 2 + hf], a_f[mf], bb);
                    }
            }
        }
        CPA_WAIT1();
        __syncthreads();
    }
#undef ISSUE

    const int rbase = m0 + wm * 32 + (lane >> 2);
    const int cb = n0 + wn * 64 + (lane & 3) * 2;
#pragma unroll
    for (int mf = 0; mf < 2; mf++)
#pragma unroll
        for (int nf = 0; nf < 8; nf++) {
            int rr = rbase + mf * 16;
            int cc = cb + nf * 8;
            float2 v0 = make_float2(acc[mf][nf][0], acc[mf][nf][1]);
            float2 v1 = make_float2(acc[mf][nf][2], acc[mf][nf][3]);
            if (bias) {
                float2 bb = *(const float2*)(bias + cc);
                v0.x += bb.x; v0.y += bb.y;
                v1.x += bb.x; v1.y += bb.y;
            }
            if (mode == 0) {
                *(float2*)(Cf + (size_t)rr * ldc + cc) = v0;
                *(float2*)(Cf + (size_t)(rr + 8) * ldc + cc) = v1;
            } else {
                *(uint32_t*)(Ch + (size_t)rr * ldc + cc) = pack2(v0.x, v0.y);
                *(uint32_t*)(Ch + (size_t)(rr + 8) * ldc + cc) = pack2(v1.x, v1.y);
            }
        }
}

// ---------------------------------------------------------------------------
// Tensor-core attention (R10 form): Q, K, V fp16 in; AO fp16 out.
// One head (64x64) per 128-thread block; warp w owns q-rows 16w..16w+15.
// ---------------------------------------------------------------------------
#define ALD 72

__global__ __launch_bounds__(128)
void attn_mma_kernel(const __half* __restrict__ Qhg, const __half* __restrict__ Khg,
                     const __half* __restrict__ Vhg, __half* __restrict__ AOh)
{
    __shared__ __align__(16) __half QH[64 * ALD];
    __shared__ __align__(16) __half KH[64 * ALD];
    __shared__ __align__(16) __half VH[64 * ALD];

    const int tid = threadIdx.x, lane = tid & 31, w = tid >> 5;
    const size_t base = (size_t)blockIdx.x * 4096;

#pragma unroll
    for (int i = 0; i < 4; i++) {
        int f = i * 128 + tid;             // 0..511
        int r = f >> 3, c = (f & 7) << 3;
        uint32_t off = 2 * (r * ALD + c);
        size_t g = base + r * 64 + c;
        *(uint4*)((char*)QH + off) = *(const uint4*)(Qhg + g);
        *(uint4*)((char*)KH + off) = *(const uint4*)(Khg + g);
        *(uint4*)((char*)VH + off) = *(const uint4*)(Vhg + g);
    }
    __syncthreads();

    const int lr = lane & 15, lc = lane >> 4;
    const uint32_t qh = smem_u32(QH), kh = smem_u32(KH), vh = smem_u32(VH);

    float S[8][4];
#pragma unroll
    for (int i = 0; i < 8; i++)
#pragma unroll
        for (int j = 0; j < 4; j++) S[i][j] = 0.f;

#pragma unroll
    for (int ks = 0; ks < 4; ks++) {
        uint32_t a_f[4];
        uint32_t adr = 2 * ((w * 16 + lr) * ALD + ks * 16 + lc * 8);
        ldm4(a_f, qh + adr);
#pragma unroll
        for (int nb = 0; nb < 4; nb++) {
            uint32_t badr = 2 * ((nb * 16 + (lane & 7) + (lane >> 4) * 8) * ALD
                                 + ks * 16 + ((lane >> 3) & 1) * 8);
            uint32_t b_h[4];
            ldm4(b_h, kh + badr);
#pragma unroll
            for (int hf = 0; hf < 2; hf++) {
                uint32_t bb[2] = {b_h[hf * 2], b_h[hf * 2 + 1]};
                mma16816(S[nb * 2 + hf], a_f, bb);
            }
        }
    }

    float mlo = -1e30f, mhi = -1e30f;
#pragma unroll
    for (int nf = 0; nf < 8; nf++) {
        S[nf][0] *= 0.125f; S[nf][1] *= 0.125f;
        S[nf][2] *= 0.125f; S[nf][3] *= 0.125f;
        mlo = fmaxf(mlo, fmaxf(S[nf][0], S[nf][1]));
        mhi = fmaxf(mhi, fmaxf(S[nf][2], S[nf][3]));
    }
    mlo = fmaxf(mlo, __shfl_xor_sync(0xffffffffu, mlo, 1));
    mlo = fmaxf(mlo, __shfl_xor_sync(0xffffffffu, mlo, 2));
    mhi = fmaxf(mhi, __shfl_xor_sync(0xffffffffu, mhi, 1));
    mhi = fmaxf(mhi, __shfl_xor_sync(0xffffffffu, mhi, 2));

    float slo = 0.f, shi = 0.f;
#pragma unroll
    for (int nf = 0; nf < 8; nf++) {
        S[nf][0] = __expf(S[nf][0] - mlo); slo += S[nf][0];
        S[nf][1] = __expf(S[nf][1] - mlo); slo += S[nf][1];
        S[nf][2] = __expf(S[nf][2] - mhi); shi += S[nf][2];
        S[nf][3] = __expf(S[nf][3] - mhi); shi += S[nf][3];
    }
    slo += __shfl_xor_sync(0xffffffffu, slo, 1);
    slo += __shfl_xor_sync(0xffffffffu, slo, 2);
    shi += __shfl_xor_sync(0xffffffffu, shi, 1);
    shi += __shfl_xor_sync(0xffffffffu, shi, 2);
    const float ilo = 1.f / slo, ihi = 1.f / shi;
#pragma unroll
    for (int nf = 0; nf < 8; nf++) {
        S[nf][0] *= ilo; S[nf][1] *= ilo;
        S[nf][2] *= ihi; S[nf][3] *= ihi;
    }

    uint32_t p_h[4][4];
#pragma unroll
    for (int j = 0; j < 4; j++) {
#pragma unroll
        for (int q = 0; q < 2; q++) {
            const float* s = (q == 0) ? S[2 * j] : S[2 * j + 1];
            p_h[j][q * 2 + 0] = pack2(s[0], s[1]);
            p_h[j][q * 2 + 1] = pack2(s[2], s[3]);
        }
    }

    float O[8][4];
#pragma unroll
    for (int i = 0; i < 8; i++)
#pragma unroll
        for (int j = 0; j < 4; j++) O[i][j] = 0.f;

#pragma unroll
    for (int j = 0; j < 4; j++) {
#pragma unroll
        for (int nb = 0; nb < 4; nb++) {
            uint32_t badr = 2 * ((j * 16 + lr) * ALD + nb * 16 + lc * 8);
            uint32_t b_h[4];
            ldm4t(b_h, vh + badr);
#pragma unroll
            for (int hf = 0; hf < 2; hf++) {
                uint32_t bb[2] = {b_h[hf * 2], b_h[hf * 2 + 1]};
                mma16816(O[nb * 2 + hf], p_h[j], bb);
            }
        }
    }

    const size_t ob = base + (size_t)(w * 16 + (lane >> 2)) * 64 + (lane & 3) * 2;
#pragma unroll
    for (int nf = 0; nf < 8; nf++) {
        *(uint32_t*)(AOh + ob + nf * 8)       = pack2(O[nf][0], O[nf][1]);
        *(uint32_t*)(AOh + ob + 512 + nf * 8) = pack2(O[nf][2], O[nf][3]);
    }
}

// ---------------------------------------------------------------------------
// Reduce NSPLIT split-K partials + bias -> out (512x512).
// ---------------------------------------------------------------------------
__global__ void reduce_out_kernel(const float4* __restrict__ part,
                                  const float4* __restrict__ bo4,
                                  float4* __restrict__ out)
{
    int i = blockIdx.x * 256 + threadIdx.x;     // 0..65535
    float4 s = bo4[i & 127];
#pragma unroll
    for (int p = 0; p < NSPLIT; p++) {
        float4 v = part[(size_t)p * 65536 + i];
        s.x += v.x; s.y += v.y; s.z += v.z; s.w += v.w;
    }
    out[i] = s;
}

// ---------------------------------------------------------------------------
extern "C" void kernel_launch(void* const* d_in, const int* in_sizes, int n_in,
                              void* d_out, int out_size)
{
    const float* x  = (const float*)d_in[0];
    const float* z  = (const float*)d_in[1];
    const float* Wq = (const float*)d_in[2];
    const float* bq = (const float*)d_in[3];
    const float* Wk = (const float*)d_in[4];
    const float* bk = (const float*)d_in[5];
    const float* Wv = (const float*)d_in[6];
    const float* bv = (const float*)d_in[7];
    const float* Wo = (const float*)d_in[8];
    const float* bo = (const float*)d_in[9];
    float* out = (float*)d_out;

    __half *Qh, *Kh, *Vh, *AOh, *xh, *zh;
    __half *Wqh, *Wkh, *Wvh, *Woh;
    float* Part;
    cudaGetSymbolAddress((void**)&Qh,  g_Qh);
    cudaGetSymbolAddress((void**)&Kh,  g_Kh);
    cudaGetSymbolAddress((void**)&Vh,  g_Vh);
    cudaGetSymbolAddress((void**)&AOh, g_AOh);
    cudaGetSymbolAddress((void**)&Part, g_part);
    cudaGetSymbolAddress((void**)&xh,  g_xh);
    cudaGetSymbolAddress((void**)&zh,  g_zh);
    cudaGetSymbolAddress((void**)&Wqh, g_Wqh);
    cudaGetSymbolAddress((void**)&Wkh, g_Wkh);
    cudaGetSymbolAddress((void**)&Wvh, g_Wvh);
    cudaGetSymbolAddress((void**)&Woh, g_Woh);

    static cudaStream_t s1 = nullptr, s2 = nullptr, s3 = nullptr;
    static cudaEvent_t ev0, evz, evx, evq, evk, evv;
    if (!s1) {
        cudaStreamCreateWithFlags(&s1, cudaStreamNonBlocking);
        cudaStreamCreateWithFlags(&s2, cudaStreamNonBlocking);
        cudaStreamCreateWithFlags(&s3, cudaStreamNonBlocking);
        cudaEventCreateWithFlags(&ev0, cudaEventDisableTiming);
        cudaEventCreateWithFlags(&evz, cudaEventDisableTiming);
        cudaEventCreateWithFlags(&evx, cudaEventDisableTiming);
        cudaEventCreateWithFlags(&evq, cudaEventDisableTiming);
        cudaEventCreateWithFlags(&evk, cudaEventDisableTiming);
        cudaEventCreateWithFlags(&evv, cudaEventDisableTiming);
        cudaFuncSetAttribute(gemm_mma7_kernel,
                             cudaFuncAttributeMaxDynamicSharedMemorySize, GSMEM);
    }

    // Fork side streams from the origin stream.
    cudaEventRecord(ev0, 0);
    cudaStreamWaitEvent(s1, ev0, 0);
    cudaStreamWaitEvent(s2, ev0, 0);
    cudaStreamWaitEvent(s3, ev0, 0);

    // s0: activation rounding (+Wo rounding, overlapped by side streams)
    conv_round_kernel<<<128, 256>>>((const float4*)z, (uint2*)zh, 32768);
    cudaEventRecord(evz, 0);
    conv_round_kernel<<<256, 256>>>((const float4*)x, (uint2*)xh, 65536);
    cudaEventRecord(evx, 0);
    conv_round_kernel<<<16384, 256>>>((const float4*)Wo, (uint2*)Woh, 4194304);

    dim3 gQKV(DTOT / 128, TOK / 128, 1);

    // s1: Wq conversion + Q projection (fp16)
    conv_round_kernel<<<8192, 256, 0, s1>>>((const float4*)Wq, (uint2*)Wqh, 2097152);
    cudaStreamWaitEvent(s1, evz, 0);
    gemm_mma7_kernel<<<gQKV, 256, GSMEM, s1>>>(zh, 256, Wqh, DTOT, bq, 2,
                                               nullptr, Qh, DTOT, 0, 256);
    cudaEventRecord(evq, s1);

    // s2: Wk conversion + K projection
    conv_round_kernel<<<16384, 256, 0, s2>>>((const float4*)Wk, (uint2*)Wkh, 4194304);
    cudaStreamWaitEvent(s2, evx, 0);
    gemm_mma7_kernel<<<gQKV, 256, GSMEM, s2>>>(xh, 512, Wkh, DTOT, bk, 2,
                                               nullptr, Kh, DTOT, 0, 512);
    cudaEventRecord(evk, s2);

    // s3: Wv conversion + V projection
    conv_round_kernel<<<16384, 256, 0, s3>>>((const float4*)Wv, (uint2*)Wvh, 4194304);
    cudaStreamWaitEvent(s3, evx, 0);
    gemm_mma7_kernel<<<gQKV, 256, GSMEM, s3>>>(xh, 512, Wvh, DTOT, bv, 2,
                                               nullptr, Vh, DTOT, 0, 512);
    cudaEventRecord(evv, s3);

    // join back to s0
    cudaStreamWaitEvent(0, evq, 0);
    cudaStreamWaitEvent(0, evk, 0);
    cudaStreamWaitEvent(0, evv, 0);

    // Attention: 4096 heads; writes AO fp16
    attn_mma_kernel<<<4096, 128>>>(Qh, Kh, Vh, AOh);

    // Output projection: split-K partials then reduce (+bias)
    dim3 gO(512 / 128, 512 / 128, NSPLIT);
    gemm_mma7_kernel<<<gO, 256, GSMEM>>>(AOh, DTOT, Woh, 512, nullptr, 0,
                                         Part, nullptr, 512,
                                         (size_t)512 * 512, DTOT / NSPLIT);

    reduce_out_kernel<<<256, 256>>>((const float4*)Part, (const float4*)bo,
                                    (float4*)out);
}

// round 14
// speedup vs baseline: 1.0449x; 1.0349x over previous
#include <cuda_runtime.h>
#include <cuda_fp16.h>
#include <cstdint>

// ---------------------------------------------------------------------------
//   x: [512,512]  z: [512,256]
//   Wq: [256,32768]  Wk/Wv: [512,32768]  Wo: [32768,512]
// ---------------------------------------------------------------------------
#define TOK   512
#define DTOT  32768
#define NSPLIT 16

typedef unsigned long long ull;

__device__ __half g_Qh[TOK * (size_t)DTOT];
__device__ __half g_Kh[TOK * (size_t)DTOT];
__device__ __half g_Vh[TOK * (size_t)DTOT];
__device__ __half g_AOh[TOK * (size_t)DTOT];
__device__ float  g_part[NSPLIT * 512 * 512];
__device__ __half g_xh[512 * 512];
__device__ __half g_zh[512 * 256];
__device__ __half g_Wqh[256 * (size_t)DTOT];
__device__ __half g_Wkh[512 * (size_t)DTOT];
__device__ __half g_Wvh[512 * (size_t)DTOT];
__device__ __half g_Woh[(size_t)DTOT * 512];

// ---------------------------------------------------------------------------
// helpers
// ---------------------------------------------------------------------------
__device__ __forceinline__ uint32_t smem_u32(const void* p) {
    uint32_t a;
    asm("{ .reg .u64 t; cvta.to.shared.u64 t, %1; cvt.u32.u64 %0, t; }" : "=r"(a) : "l"(p));
    return a;
}
__device__ __forceinline__ void ldm4(uint32_t r[4], uint32_t addr) {
    asm volatile("ldmatrix.sync.aligned.m8n8.x4.shared.b16 {%0,%1,%2,%3}, [%4];"
                 : "=r"(r[0]), "=r"(r[1]), "=r"(r[2]), "=r"(r[3]) : "r"(addr));
}
__device__ __forceinline__ void ldm4t(uint32_t r[4], uint32_t addr) {
    asm volatile("ldmatrix.sync.aligned.m8n8.x4.trans.shared.b16 {%0,%1,%2,%3}, [%4];"
                 : "=r"(r[0]), "=r"(r[1]), "=r"(r[2]), "=r"(r[3]) : "r"(addr));
}
__device__ __forceinline__ void mma16816(float c[4], const uint32_t a[4], const uint32_t b[2]) {
    asm volatile(
        "mma.sync.aligned.m16n8k16.row.col.f32.f16.f16.f32 "
        "{%0,%1,%2,%3}, {%4,%5,%6,%7}, {%8,%9}, {%0,%1,%2,%3};"
        : "+f"(c[0]), "+f"(c[1]), "+f"(c[2]), "+f"(c[3])
        : "r"(a[0]), "r"(a[1]), "r"(a[2]), "r"(a[3]), "r"(b[0]), "r"(b[1]));
}
__device__ __forceinline__ uint32_t pack2(float e0, float e1) {   // lo=e0, hi=e1
    uint32_t r;
    asm("cvt.rn.f16x2.f32 %0, %1, %2;" : "=r"(r) : "f"(e1), "f"(e0));
    return r;
}
#define CPA16(sm, gm) asm volatile("cp.async.ca.shared.global [%0], [%1], 16;" :: "r"(sm), "l"(gm))
#define CPA_COMMIT()  asm volatile("cp.async.commit_group;" ::: "memory")
#define CPA_WAIT1()   asm volatile("cp.async.wait_group 1;" ::: "memory")

// ---------------------------------------------------------------------------
// fp32 -> fp16 round
// ---------------------------------------------------------------------------
__global__ void conv_round_kernel(const float4* __restrict__ src,
                                  uint2* __restrict__ dst, int n4)
{
    int i = blockIdx.x * 256 + threadIdx.x;
    if (i >= n4) return;
    float4 v = src[i];
    uint2 o;
    o.x = pack2(v.x, v.y);
    o.y = pack2(v.z, v.w);
    dst[i] = o;
}

// ---------------------------------------------------------------------------
// GEMM C = A @ B (+bias): A fp16, B fp16.   (R10 configuration, verbatim)
// 512 threads, block tile 128x256, BK=64; warp tile 32x64 (4x4 warp grid).
// 3-stage cp.async pipeline.
// mode: 0 = fp32 C; 2 = fp16 C   (+bias if non-null)
// ---------------------------------------------------------------------------
#define LDA_S 72
#define LDB_S 264
#define ASTG  18432
#define BSTG  33792
#define BOFF  (3 * ASTG)
#define GSMEM (BOFF + 3 * BSTG)     // 156672

__global__ __launch_bounds__(512)
void gemm_mma6_kernel(const __half* __restrict__ Ahg, int lda,
                      const __half* __restrict__ Bhg, int ldb,
                      const float* __restrict__ bias, int mode,
                      float* __restrict__ Cf, __half* __restrict__ Ch, int ldc,
                      size_t csplit, int ksize)
{
    extern __shared__ __align__(16) char dsm[];
    const int tid = threadIdx.x, lane = tid & 31, wid = tid >> 5;
    const int wm = wid & 3, wn = wid >> 2;
    const int n0 = blockIdx.x << 8, m0 = blockIdx.y << 7;
    const int kbeg = blockIdx.z * ksize;
    if (Cf) Cf += (size_t)blockIdx.z * csplit;

    const uint32_t smb = smem_u32(dsm);

    float acc[2][8][4];
#pragma unroll
    for (int i = 0; i < 2; i++)
#pragma unroll
        for (int j = 0; j < 8; j++)
#pragma unroll
            for (int k = 0; k < 4; k++) acc[i][j][k] = 0.f;

    const int lr = lane & 15, lc = lane >> 4;

    const int a_r = tid >> 3, a_c = (tid & 7) << 3;
    const int b_r = tid >> 5, b_c = (tid & 31) << 3;

    const __half* Aph = Ahg + (size_t)(m0 + a_r) * lda + kbeg + a_c;
    const __half* Bp  = Bhg + (size_t)(kbeg + b_r) * ldb + n0 + b_c;

    const uint32_t a_dst0 = smb + a_r * (2 * LDA_S) + 2 * a_c;
    const uint32_t a_dst1 = smb + (a_r + 64) * (2 * LDA_S) + 2 * a_c;
    const uint32_t b_dst  = smb + BOFF + b_r * (2 * LDB_S) + 2 * b_c;

#define ISSUE(ch, s) do { \
    CPA16(a_dst0 + (s) * ASTG, Aph + (ch) * 64); \
    CPA16(a_dst1 + (s) * ASTG, Aph + (size_t)64 * lda + (ch) * 64); \
    _Pragma("unroll") \
    for (int p = 0; p < 4; p++) \
        CPA16(b_dst + (s) * BSTG + p * 16 * (2 * LDB_S), \
              Bp + (size_t)((ch) * 64 + p * 16) * ldb); } while (0)

    const int nch = ksize >> 6;
    ISSUE(0, 0); CPA_COMMIT();
    if (nch > 1) { ISSUE(1, 1); CPA_COMMIT(); }
    else CPA_COMMIT();
    CPA_WAIT1();
    __syncthreads();

    for (int ch = 0; ch < nch; ch++) {
        const int cur = ch % 3;
        if (ch + 2 < nch) ISSUE(ch + 2, (ch + 2) % 3);
        CPA_COMMIT();

        const uint32_t ahb = smb + cur * ASTG;
        const uint32_t bhb = smb + BOFF + cur * BSTG;

#pragma unroll
        for (int ks = 0; ks < 4; ks++) {
            uint32_t a_f[2][4];
#pragma unroll
            for (int mf = 0; mf < 2; mf++) {
                uint32_t adr = 2 * ((wm * 32 + mf * 16 + lr) * LDA_S + ks * 16 + lc * 8);
                ldm4(a_f[mf], ahb + adr);
            }
#pragma unroll
            for (int nb = 0; nb < 4; nb++) {
                uint32_t b_f[4];
                uint32_t adr = 2 * ((ks * 16 + lr) * LDB_S + wn * 64 + nb * 16 + lc * 8);
                ldm4t(b_f, bhb + adr);
#pragma unroll
                for (int mf = 0; mf < 2; mf++)
#pragma unroll
                    for (int hf = 0; hf < 2; hf++) {
                        uint32_t bb[2] = {b_f[hf * 2], b_f[hf * 2 + 1]};
                        mma16816(acc[mf][nb * 2 + hf], a_f[mf], bb);
                    }
            }
        }
        CPA_WAIT1();
        __syncthreads();
    }
#undef ISSUE

    const int rbase = m0 + wm * 32 + (lane >> 2);
    const int cb = n0 + wn * 64 + (lane & 3) * 2;
#pragma unroll
    for (int mf = 0; mf < 2; mf++)
#pragma unroll
        for (int nf = 0; nf < 8; nf++) {
            int rr = rbase + mf * 16;
            int cc = cb + nf * 8;
            float2 v0 = make_float2(acc[mf][nf][0], acc[mf][nf][1]);
            float2 v1 = make_float2(acc[mf][nf][2], acc[mf][nf][3]);
            if (bias) {
                float2 bb = *(const float2*)(bias + cc);
                v0.x += bb.x; v0.y += bb.y;
                v1.x += bb.x; v1.y += bb.y;
            }
            if (mode == 0) {
                *(float2*)(Cf + (size_t)rr * ldc + cc) = v0;
                *(float2*)(Cf + (size_t)(rr + 8) * ldc + cc) = v1;
            } else {
                *(uint32_t*)(Ch + (size_t)rr * ldc + cc) = pack2(v0.x, v0.y);
                *(uint32_t*)(Ch + (size_t)(rr + 8) * ldc + cc) = pack2(v1.x, v1.y);
            }
        }
}

// ---------------------------------------------------------------------------
// Tensor-core attention (R10 form): Q, K, V fp16 in; AO fp16 out.
// One head (64x64) per 128-thread block; warp w owns q-rows 16w..16w+15.
// ---------------------------------------------------------------------------
#define ALD 72

__global__ __launch_bounds__(128)
void attn_mma_kernel(const __half* __restrict__ Qhg, const __half* __restrict__ Khg,
                     const __half* __restrict__ Vhg, __half* __restrict__ AOh)
{
    __shared__ __align__(16) __half QH[64 * ALD];
    __shared__ __align__(16) __half KH[64 * ALD];
    __shared__ __align__(16) __half VH[64 * ALD];

    const int tid = threadIdx.x, lane = tid & 31, w = tid >> 5;
    const size_t base = (size_t)blockIdx.x * 4096;

#pragma unroll
    for (int i = 0; i < 4; i++) {
        int f = i * 128 + tid;             // 0..511
        int r = f >> 3, c = (f & 7) << 3;
        uint32_t off = 2 * (r * ALD + c);
        size_t g = base + r * 64 + c;
        *(uint4*)((char*)QH + off) = *(const uint4*)(Qhg + g);
        *(uint4*)((char*)KH + off) = *(const uint4*)(Khg + g);
        *(uint4*)((char*)VH + off) = *(const uint4*)(Vhg + g);
    }
    __syncthreads();

    const int lr = lane & 15, lc = lane >> 4;
    const uint32_t qh = smem_u32(QH), kh = smem_u32(KH), vh = smem_u32(VH);

    float S[8][4];
#pragma unroll
    for (int i = 0; i < 8; i++)
#pragma unroll
        for (int j = 0; j < 4; j++) S[i][j] = 0.f;

#pragma unroll
    for (int ks = 0; ks < 4; ks++) {
        uint32_t a_f[4];
        uint32_t adr = 2 * ((w * 16 + lr) * ALD + ks * 16 + lc * 8);
        ldm4(a_f, qh + adr);
#pragma unroll
        for (int nb = 0; nb < 4; nb++) {
            uint32_t badr = 2 * ((nb * 16 + (lane & 7) + (lane >> 4) * 8) * ALD
                                 + ks * 16 + ((lane >> 3) & 1) * 8);
            uint32_t b_h[4];
            ldm4(b_h, kh + badr);
#pragma unroll
            for (int hf = 0; hf < 2; hf++) {
                uint32_t bb[2] = {b_h[hf * 2], b_h[hf * 2 + 1]};
                mma16816(S[nb * 2 + hf], a_f, bb);
            }
        }
    }

    float mlo = -1e30f, mhi = -1e30f;
#pragma unroll
    for (int nf = 0; nf < 8; nf++) {
        S[nf][0] *= 0.125f; S[nf][1] *= 0.125f;
        S[nf][2] *= 0.125f; S[nf][3] *= 0.125f;
        mlo = fmaxf(mlo, fmaxf(S[nf][0], S[nf][1]));
        mhi = fmaxf(mhi, fmaxf(S[nf][2], S[nf][3]));
    }
    mlo = fmaxf(mlo, __shfl_xor_sync(0xffffffffu, mlo, 1));
    mlo = fmaxf(mlo, __shfl_xor_sync(0xffffffffu, mlo, 2));
    mhi = fmaxf(mhi, __shfl_xor_sync(0xffffffffu, mhi, 1));
    mhi = fmaxf(mhi, __shfl_xor_sync(0xffffffffu, mhi, 2));

    float slo = 0.f, shi = 0.f;
#pragma unroll
    for (int nf = 0; nf < 8; nf++) {
        S[nf][0] = __expf(S[nf][0] - mlo); slo += S[nf][0];
        S[nf][1] = __expf(S[nf][1] - mlo); slo += S[nf][1];
        S[nf][2] = __expf(S[nf][2] - mhi); shi += S[nf][2];
        S[nf][3] = __expf(S[nf][3] - mhi); shi += S[nf][3];
    }
    slo += __shfl_xor_sync(0xffffffffu, slo, 1);
    slo += __shfl_xor_sync(0xffffffffu, slo, 2);
    shi += __shfl_xor_sync(0xffffffffu, shi, 1);
    shi += __shfl_xor_sync(0xffffffffu, shi, 2);
    const float ilo = 1.f / slo, ihi = 1.f / shi;
#pragma unroll
    for (int nf = 0; nf < 8; nf++) {
        S[nf][0] *= ilo; S[nf][1] *= ilo;
        S[nf][2] *= ihi; S[nf][3] *= ihi;
    }

    uint32_t p_h[4][4];
#pragma unroll
    for (int j = 0; j < 4; j++) {
#pragma unroll
        for (int q = 0; q < 2; q++) {
            const float* s = (q == 0) ? S[2 * j] : S[2 * j + 1];
            p_h[j][q * 2 + 0] = pack2(s[0], s[1]);
            p_h[j][q * 2 + 1] = pack2(s[2], s[3]);
        }
    }

    float O[8][4];
#pragma unroll
    for (int i = 0; i < 8; i++)
#pragma unroll
        for (int j = 0; j < 4; j++) O[i][j] = 0.f;

#pragma unroll
    for (int j = 0; j < 4; j++) {
#pragma unroll
        for (int nb = 0; nb < 4; nb++) {
            uint32_t badr = 2 * ((j * 16 + lr) * ALD + nb * 16 + lc * 8);
            uint32_t b_h[4];
            ldm4t(b_h, vh + badr);
#pragma unroll
            for (int hf = 0; hf < 2; hf++) {
                uint32_t bb[2] = {b_h[hf * 2], b_h[hf * 2 + 1]};
                mma16816(O[nb * 2 + hf], p_h[j], bb);
            }
        }
    }

    const size_t ob = base + (size_t)(w * 16 + (lane >> 2)) * 64 + (lane & 3) * 2;
#pragma unroll
    for (int nf = 0; nf < 8; nf++) {
        *(uint32_t*)(AOh + ob + nf * 8)       = pack2(O[nf][0], O[nf][1]);
        *(uint32_t*)(AOh + ob + 512 + nf * 8) = pack2(O[nf][2], O[nf][3]);
    }
}

// ---------------------------------------------------------------------------
// Reduce NSPLIT split-K partials + bias -> out (512x512).
// ---------------------------------------------------------------------------
__global__ void reduce_out_kernel(const float4* __restrict__ part,
                                  const float4* __restrict__ bo4,
                                  float4* __restrict__ out)
{
    int i = blockIdx.x * 256 + threadIdx.x;     // 0..65535
    float4 s = bo4[i & 127];
#pragma unroll
    for (int p = 0; p < NSPLIT; p++) {
        float4 v = part[(size_t)p * 65536 + i];
        s.x += v.x; s.y += v.y; s.z += v.z; s.w += v.w;
    }
    out[i] = s;
}

// ---------------------------------------------------------------------------
extern "C" void kernel_launch(void* const* d_in, const int* in_sizes, int n_in,
                              void* d_out, int out_size)
{
    const float* x  = (const float*)d_in[0];
    const float* z  = (const float*)d_in[1];
    const float* Wq = (const float*)d_in[2];
    const float* bq = (const float*)d_in[3];
    const float* Wk = (const float*)d_in[4];
    const float* bk = (const float*)d_in[5];
    const float* Wv = (const float*)d_in[6];
    const float* bv = (const float*)d_in[7];
    const float* Wo = (const float*)d_in[8];
    const float* bo = (const float*)d_in[9];
    float* out = (float*)d_out;

    __half *Qh, *Kh, *Vh, *AOh, *xh, *zh;
    __half *Wqh, *Wkh, *Wvh, *Woh;
    float* Part;
    cudaGetSymbolAddress((void**)&Qh,  g_Qh);
    cudaGetSymbolAddress((void**)&Kh,  g_Kh);
    cudaGetSymbolAddress((void**)&Vh,  g_Vh);
    cudaGetSymbolAddress((void**)&AOh, g_AOh);
    cudaGetSymbolAddress((void**)&Part, g_part);
    cudaGetSymbolAddress((void**)&xh,  g_xh);
    cudaGetSymbolAddress((void**)&zh,  g_zh);
    cudaGetSymbolAddress((void**)&Wqh, g_Wqh);
    cudaGetSymbolAddress((void**)&Wkh, g_Wkh);
    cudaGetSymbolAddress((void**)&Wvh, g_Wvh);
    cudaGetSymbolAddress((void**)&Woh, g_Woh);

    static cudaStream_t s1 = nullptr, s2 = nullptr, s3 = nullptr;
    static cudaEvent_t ev0, evz, evx, evq, evk, evv;
    if (!s1) {
        cudaStreamCreateWithFlags(&s1, cudaStreamNonBlocking);
        cudaStreamCreateWithFlags(&s2, cudaStreamNonBlocking);
        cudaStreamCreateWithFlags(&s3, cudaStreamNonBlocking);
        cudaEventCreateWithFlags(&ev0, cudaEventDisableTiming);
        cudaEventCreateWithFlags(&evz, cudaEventDisableTiming);
        cudaEventCreateWithFlags(&evx, cudaEventDisableTiming);
        cudaEventCreateWithFlags(&evq, cudaEventDisableTiming);
        cudaEventCreateWithFlags(&evk, cudaEventDisableTiming);
        cudaEventCreateWithFlags(&evv, cudaEventDisableTiming);
        cudaFuncSetAttribute(gemm_mma6_kernel,
                             cudaFuncAttributeMaxDynamicSharedMemorySize, GSMEM);
    }

    // Fork side streams from the origin stream.
    cudaEventRecord(ev0, 0);
    cudaStreamWaitEvent(s1, ev0, 0);
    cudaStreamWaitEvent(s2, ev0, 0);
    cudaStreamWaitEvent(s3, ev0, 0);

    // s0: activation rounding (+Wo rounding, overlapped by side streams)
    conv_round_kernel<<<128, 256>>>((const float4*)z, (uint2*)zh, 32768);
    cudaEventRecord(evz, 0);
    conv_round_kernel<<<256, 256>>>((const float4*)x, (uint2*)xh, 65536);
    cudaEventRecord(evx, 0);
    conv_round_kernel<<<16384, 256>>>((const float4*)Wo, (uint2*)Woh, 4194304);

    dim3 gQKV(DTOT / 256, TOK / 128, 1);

    // s1: Wq conversion + Q projection (fp16)
    conv_round_kernel<<<8192, 256, 0, s1>>>((const float4*)Wq, (uint2*)Wqh, 2097152);
    cudaStreamWaitEvent(s1, evz, 0);
    gemm_mma6_kernel<<<gQKV, 512, GSMEM, s1>>>(zh, 256, Wqh, DTOT, bq, 2,
                                               nullptr, Qh, DTOT, 0, 256);
    cudaEventRecord(evq, s1);

    // s2: Wk conversion + K projection
    conv_round_kernel<<<16384, 256, 0, s2>>>((const float4*)Wk, (uint2*)Wkh, 4194304);
    cudaStreamWaitEvent(s2, evx, 0);
    gemm_mma6_kernel<<<gQKV, 512, GSMEM, s2>>>(xh, 512, Wkh, DTOT, bk, 2,
                                               nullptr, Kh, DTOT, 0, 512);
    cudaEventRecord(evk, s2);

    // s3: Wv conversion + V projection
    conv_round_kernel<<<16384, 256, 0, s3>>>((const float4*)Wv, (uint2*)Wvh, 4194304);
    cudaStreamWaitEvent(s3, evx, 0);
    gemm_mma6_kernel<<<gQKV, 512, GSMEM, s3>>>(xh, 512, Wvh, DTOT, bv, 2,
                                               nullptr, Vh, DTOT, 0, 512);
    cudaEventRecord(evv, s3);

    // join back to s0
    cudaStreamWaitEvent(0, evq, 0);
    cudaStreamWaitEvent(0, evk, 0);
    cudaStreamWaitEvent(0, evv, 0);

    // Attention: 4096 heads; writes AO fp16
    attn_mma_kernel<<<4096, 128>>>(Qh, Kh, Vh, AOh);

    // Output projection: split-K partials (single wave: 2x4x16 = 128 CTAs)
    dim3 gO(512 / 256, 512 / 128, NSPLIT);
    gemm_mma6_kernel<<<gO, 512, GSMEM>>>(AOh, DTOT, Woh, 512, nullptr, 0,
                                         Part, nullptr, 512,
                                         (size_t)512 * 512, DTOT / NSPLIT);

    reduce_out_kernel<<<256, 256>>>((const float4*)Part, (const float4*)bo,
                                    (float4*)out);
}

// round 15
// speedup vs baseline: 1.0831x; 1.0366x over previous
#include <cuda_runtime.h>
#include <cuda_fp16.h>
#include <cstdint>

// ---------------------------------------------------------------------------
//   x: [512,512]  z: [512,256]
//   Wq: [256,32768]  Wk/Wv: [512,32768]  Wo: [32768,512]
// ---------------------------------------------------------------------------
#define TOK   512
#define DTOT  32768
#define NSPLIT 16

typedef unsigned long long ull;

__device__ __half g_Qh[TOK * (size_t)DTOT];
__device__ __half g_Kh[TOK * (size_t)DTOT];
__device__ __half g_Vh[TOK * (size_t)DTOT];
__device__ __half g_AOh[TOK * (size_t)DTOT];
__device__ float  g_part[NSPLIT * 512 * 512];
__device__ __half g_xh[512 * 512];
__device__ __half g_zh[512 * 256];
__device__ __half g_Wqh[256 * (size_t)DTOT];
__device__ __half g_Wkh[512 * (size_t)DTOT];
__device__ __half g_Wvh[512 * (size_t)DTOT];
__device__ __half g_Woh[(size_t)DTOT * 512];

// ---------------------------------------------------------------------------
// helpers
// ---------------------------------------------------------------------------
__device__ __forceinline__ uint32_t smem_u32(const void* p) {
    uint32_t a;
    asm("{ .reg .u64 t; cvta.to.shared.u64 t, %1; cvt.u32.u64 %0, t; }" : "=r"(a) : "l"(p));
    return a;
}
__device__ __forceinline__ void ldm4(uint32_t r[4], uint32_t addr) {
    asm volatile("ldmatrix.sync.aligned.m8n8.x4.shared.b16 {%0,%1,%2,%3}, [%4];"
                 : "=r"(r[0]), "=r"(r[1]), "=r"(r[2]), "=r"(r[3]) : "r"(addr));
}
__device__ __forceinline__ void ldm4t(uint32_t r[4], uint32_t addr) {
    asm volatile("ldmatrix.sync.aligned.m8n8.x4.trans.shared.b16 {%0,%1,%2,%3}, [%4];"
                 : "=r"(r[0]), "=r"(r[1]), "=r"(r[2]), "=r"(r[3]) : "r"(addr));
}
__device__ __forceinline__ void mma16816(float c[4], const uint32_t a[4], const uint32_t b[2]) {
    asm volatile(
        "mma.sync.aligned.m16n8k16.row.col.f32.f16.f16.f32 "
        "{%0,%1,%2,%3}, {%4,%5,%6,%7}, {%8,%9}, {%0,%1,%2,%3};"
        : "+f"(c[0]), "+f"(c[1]), "+f"(c[2]), "+f"(c[3])
        : "r"(a[0]), "r"(a[1]), "r"(a[2]), "r"(a[3]), "r"(b[0]), "r"(b[1]));
}
__device__ __forceinline__ uint32_t pack2(float e0, float e1) {   // lo=e0, hi=e1
    uint32_t r;
    asm("cvt.rn.f16x2.f32 %0, %1, %2;" : "=r"(r) : "f"(e1), "f"(e0));
    return r;
}
#define CPA16(sm, gm) asm volatile("cp.async.ca.shared.global [%0], [%1], 16;" :: "r"(sm), "l"(gm))
#define CPA_COMMIT()  asm volatile("cp.async.commit_group;" ::: "memory")
#define CPA_WAIT1()   asm volatile("cp.async.wait_group 1;" ::: "memory")

// ---------------------------------------------------------------------------
// fp32 -> fp16 round, 4 independent float4 per thread (MLP=4).
// n4 must be a multiple of 1024 (all our sizes are).
// ---------------------------------------------------------------------------
__global__ void conv_round_kernel(const float4* __restrict__ src,
                                  uint2* __restrict__ dst, int n4)
{
    int base = blockIdx.x * 1024 + threadIdx.x;
    float4 v[4];
#pragma unroll
    for (int j = 0; j < 4; j++) v[j] = src[base + j * 256];
#pragma unroll
    for (int j = 0; j < 4; j++) {
        uint2 o;
        o.x = pack2(v[j].x, v[j].y);
        o.y = pack2(v[j].z, v[j].w);
        dst[base + j * 256] = o;
    }
}

// ---------------------------------------------------------------------------
// GEMM C = A @ B (+bias): A fp16, B fp16.  (R10 core; M-tile on blockIdx.x
// so a full-chip wave holds ALL M-tiles of each N-tile -> B shared via L2.)
// 512 threads, block tile 128x256, BK=64; warp tile 32x64 (4x4 warp grid).
// 3-stage cp.async pipeline.
// mode: 0 = fp32 C; 2 = fp16 C   (+bias if non-null)
// ---------------------------------------------------------------------------
#define LDA_S 72
#define LDB_S 264
#define ASTG  18432
#define BSTG  33792
#define BOFF  (3 * ASTG)
#define GSMEM (BOFF + 3 * BSTG)     // 156672

__global__ __launch_bounds__(512)
void gemm_mma6_kernel(const __half* __restrict__ Ahg, int lda,
                      const __half* __restrict__ Bhg, int ldb,
                      const float* __restrict__ bias, int mode,
                      float* __restrict__ Cf, __half* __restrict__ Ch, int ldc,
                      size_t csplit, int ksize)
{
    extern __shared__ __align__(16) char dsm[];
    const int tid = threadIdx.x, lane = tid & 31, wid = tid >> 5;
    const int wm = wid & 3, wn = wid >> 2;
    const int m0 = blockIdx.x << 7, n0 = blockIdx.y << 8;   // swapped mapping
    const int kbeg = blockIdx.z * ksize;
    if (Cf) Cf += (size_t)blockIdx.z * csplit;

    const uint32_t smb = smem_u32(dsm);

    float acc[2][8][4];
#pragma unroll
    for (int i = 0; i < 2; i++)
#pragma unroll
        for (int j = 0; j < 8; j++)
#pragma unroll
            for (int k = 0; k < 4; k++) acc[i][j][k] = 0.f;

    const int lr = lane & 15, lc = lane >> 4;

    const int a_r = tid >> 3, a_c = (tid & 7) << 3;
    const int b_r = tid >> 5, b_c = (tid & 31) << 3;

    const __half* Aph = Ahg + (size_t)(m0 + a_r) * lda + kbeg + a_c;
    const __half* Bp  = Bhg + (size_t)(kbeg + b_r) * ldb + n0 + b_c;

    const uint32_t a_dst0 = smb + a_r * (2 * LDA_S) + 2 * a_c;
    const uint32_t a_dst1 = smb + (a_r + 64) * (2 * LDA_S) + 2 * a_c;
    const uint32_t b_dst  = smb + BOFF + b_r * (2 * LDB_S) + 2 * b_c;

#define ISSUE(ch, s) do { \
    CPA16(a_dst0 + (s) * ASTG, Aph + (ch) * 64); \
    CPA16(a_dst1 + (s) * ASTG, Aph + (size_t)64 * lda + (ch) * 64); \
    _Pragma("unroll") \
    for (int p = 0; p < 4; p++) \
        CPA16(b_dst + (s) * BSTG + p * 16 * (2 * LDB_S), \
              Bp + (size_t)((ch) * 64 + p * 16) * ldb); } while (0)

    const int nch = ksize >> 6;
    ISSUE(0, 0); CPA_COMMIT();
    if (nch > 1) { ISSUE(1, 1); CPA_COMMIT(); }
    else CPA_COMMIT();
    CPA_WAIT1();
    __syncthreads();

    for (int ch = 0; ch < nch; ch++) {
        const int cur = ch % 3;
        if (ch + 2 < nch) ISSUE(ch + 2, (ch + 2) % 3);
        CPA_COMMIT();

        const uint32_t ahb = smb + cur * ASTG;
        const uint32_t bhb = smb + BOFF + cur * BSTG;

#pragma unroll
        for (int ks = 0; ks < 4; ks++) {
            uint32_t a_f[2][4];
#pragma unroll
            for (int mf = 0; mf < 2; mf++) {
                uint32_t adr = 2 * ((wm * 32 + mf * 16 + lr) * LDA_S + ks * 16 + lc * 8);
                ldm4(a_f[mf], ahb + adr);
            }
#pragma unroll
            for (int nb = 0; nb < 4; nb++) {
                uint32_t b_f[4];
                uint32_t adr = 2 * ((ks * 16 + lr) * LDB_S + wn * 64 + nb * 16 + lc * 8);
                ldm4t(b_f, bhb + adr);
#pragma unroll
                for (int mf = 0; mf < 2; mf++)
#pragma unroll
                    for (int hf = 0; hf < 2; hf++) {
                        uint32_t bb[2] = {b_f[hf * 2], b_f[hf * 2 + 1]};
                        mma16816(acc[mf][nb * 2 + hf], a_f[mf], bb);
                    }
            }
        }
        CPA_WAIT1();
        __syncthreads();
    }
#undef ISSUE

    const int rbase = m0 + wm * 32 + (lane >> 2);
    const int cb = n0 + wn * 64 + (lane & 3) * 2;
#pragma unroll
    for (int mf = 0; mf < 2; mf++)
#pragma unroll
        for (int nf = 0; nf < 8; nf++) {
            int rr = rbase + mf * 16;
            int cc = cb + nf * 8;
            float2 v0 = make_float2(acc[mf][nf][0], acc[mf][nf][1]);
            float2 v1 = make_float2(acc[mf][nf][2], acc[mf][nf][3]);
            if (bias) {
                float2 bb = *(const float2*)(bias + cc);
                v0.x += bb.x; v0.y += bb.y;
                v1.x += bb.x; v1.y += bb.y;
            }
            if (mode == 0) {
                *(float2*)(Cf + (size_t)rr * ldc + cc) = v0;
                *(float2*)(Cf + (size_t)(rr + 8) * ldc + cc) = v1;
            } else {
                *(uint32_t*)(Ch + (size_t)rr * ldc + cc) = pack2(v0.x, v0.y);
                *(uint32_t*)(Ch + (size_t)(rr + 8) * ldc + cc) = pack2(v1.x, v1.y);
            }
        }
}

// ---------------------------------------------------------------------------
// Tensor-core attention (R10 form): Q, K, V fp16 in; AO fp16 out.
// One head (64x64) per 128-thread block; warp w owns q-rows 16w..16w+15.
// ---------------------------------------------------------------------------
#define ALD 72

__global__ __launch_bounds__(128)
void attn_mma_kernel(const __half* __restrict__ Qhg, const __half* __restrict__ Khg,
                     const __half* __restrict__ Vhg, __half* __restrict__ AOh)
{
    __shared__ __align__(16) __half QH[64 * ALD];
    __shared__ __align__(16) __half KH[64 * ALD];
    __shared__ __align__(16) __half VH[64 * ALD];

    const int tid = threadIdx.x, lane = tid & 31, w = tid >> 5;
    const size_t base = (size_t)blockIdx.x * 4096;

#pragma unroll
    for (int i = 0; i < 4; i++) {
        int f = i * 128 + tid;             // 0..511
        int r = f >> 3, c = (f & 7) << 3;
        uint32_t off = 2 * (r * ALD + c);
        size_t g = base + r * 64 + c;
        *(uint4*)((char*)QH + off) = *(const uint4*)(Qhg + g);
        *(uint4*)((char*)KH + off) = *(const uint4*)(Khg + g);
        *(uint4*)((char*)VH + off) = *(const uint4*)(Vhg + g);
    }
    __syncthreads();

    const int lr = lane & 15, lc = lane >> 4;
    const uint32_t qh = smem_u32(QH), kh = smem_u32(KH), vh = smem_u32(VH);

    float S[8][4];
#pragma unroll
    for (int i = 0; i < 8; i++)
#pragma unroll
        for (int j = 0; j < 4; j++) S[i][j] = 0.f;

#pragma unroll
    for (int ks = 0; ks < 4; ks++) {
        uint32_t a_f[4];
        uint32_t adr = 2 * ((w * 16 + lr) * ALD + ks * 16 + lc * 8);
        ldm4(a_f, qh + adr);
#pragma unroll
        for (int nb = 0; nb < 4; nb++) {
            uint32_t badr = 2 * ((nb * 16 + (lane & 7) + (lane >> 4) * 8) * ALD
                                 + ks * 16 + ((lane >> 3) & 1) * 8);
            uint32_t b_h[4];
            ldm4(b_h, kh + badr);
#pragma unroll
            for (int hf = 0; hf < 2; hf++) {
                uint32_t bb[2] = {b_h[hf * 2], b_h[hf * 2 + 1]};
                mma16816(S[nb * 2 + hf], a_f, bb);
            }
        }
    }

    float mlo = -1e30f, mhi = -1e30f;
#pragma unroll
    for (int nf = 0; nf < 8; nf++) {
        S[nf][0] *= 0.125f; S[nf][1] *= 0.125f;
        S[nf][2] *= 0.125f; S[nf][3] *= 0.125f;
        mlo = fmaxf(mlo, fmaxf(S[nf][0], S[nf][1]));
        mhi = fmaxf(mhi, fmaxf(S[nf][2], S[nf][3]));
    }
    mlo = fmaxf(mlo, __shfl_xor_sync(0xffffffffu, mlo, 1));
    mlo = fmaxf(mlo, __shfl_xor_sync(0xffffffffu, mlo, 2));
    mhi = fmaxf(mhi, __shfl_xor_sync(0xffffffffu, mhi, 1));
    mhi = fmaxf(mhi, __shfl_xor_sync(0xffffffffu, mhi, 2));

    float slo = 0.f, shi = 0.f;
#pragma unroll
    for (int nf = 0; nf < 8; nf++) {
        S[nf][0] = __expf(S[nf][0] - mlo); slo += S[nf][0];
        S[nf][1] = __expf(S[nf][1] - mlo); slo += S[nf][1];
        S[nf][2] = __expf(S[nf][2] - mhi); shi += S[nf][2];
        S[nf][3] = __expf(S[nf][3] - mhi); shi += S[nf][3];
    }
    slo += __shfl_xor_sync(0xffffffffu, slo, 1);
    slo += __shfl_xor_sync(0xffffffffu, slo, 2);
    shi += __shfl_xor_sync(0xffffffffu, shi, 1);
    shi += __shfl_xor_sync(0xffffffffu, shi, 2);
    const float ilo = 1.f / slo, ihi = 1.f / shi;
#pragma unroll
    for (int nf = 0; nf < 8; nf++) {
        S[nf][0] *= ilo; S[nf][1] *= ilo;
        S[nf][2] *= ihi; S[nf][3] *= ihi;
    }

    uint32_t p_h[4][4];
#pragma unroll
    for (int j = 0; j < 4; j++) {
#pragma unroll
        for (int q = 0; q < 2; q++) {
            const float* s = (q == 0) ? S[2 * j] : S[2 * j + 1];
            p_h[j][q * 2 + 0] = pack2(s[0], s[1]);
            p_h[j][q * 2 + 1] = pack2(s[2], s[3]);
        }
    }

    float O[8][4];
#pragma unroll
    for (int i = 0; i < 8; i++)
#pragma unroll
        for (int j = 0; j < 4; j++) O[i][j] = 0.f;

#pragma unroll
    for (int j = 0; j < 4; j++) {
#pragma unroll
        for (int nb = 0; nb < 4; nb++) {
            uint32_t badr = 2 * ((j * 16 + lr) * ALD + nb * 16 + lc * 8);
            uint32_t b_h[4];
            ldm4t(b_h, vh + badr);
#pragma unroll
            for (int hf = 0; hf < 2; hf++) {
                uint32_t bb[2] = {b_h[hf * 2], b_h[hf * 2 + 1]};
                mma16816(O[nb * 2 + hf], p_h[j], bb);
            }
        }
    }

    const size_t ob = base + (size_t)(w * 16 + (lane >> 2)) * 64 + (lane & 3) * 2;
#pragma unroll
    for (int nf = 0; nf < 8; nf++) {
        *(uint32_t*)(AOh + ob + nf * 8)       = pack2(O[nf][0], O[nf][1]);
        *(uint32_t*)(AOh + ob + 512 + nf * 8) = pack2(O[nf][2], O[nf][3]);
    }
}

// ---------------------------------------------------------------------------
// Reduce NSPLIT split-K partials + bias -> out (512x512).
// ---------------------------------------------------------------------------
__global__ void reduce_out_kernel(const float4* __restrict__ part,
                                  const float4* __restrict__ bo4,
                                  float4* __restrict__ out)
{
    int i = blockIdx.x * 256 + threadIdx.x;     // 0..65535
    float4 s = bo4[i & 127];
#pragma unroll
    for (int p = 0; p < NSPLIT; p++) {
        float4 v = part[(size_t)p * 65536 + i];
        s.x += v.x; s.y += v.y; s.z += v.z; s.w += v.w;
    }
    out[i] = s;
}

// ---------------------------------------------------------------------------
extern "C" void kernel_launch(void* const* d_in, const int* in_sizes, int n_in,
                              void* d_out, int out_size)
{
    const float* x  = (const float*)d_in[0];
    const float* z  = (const float*)d_in[1];
    const float* Wq = (const float*)d_in[2];
    const float* bq = (const float*)d_in[3];
    const float* Wk = (const float*)d_in[4];
    const float* bk = (const float*)d_in[5];
    const float* Wv = (const float*)d_in[6];
    const float* bv = (const float*)d_in[7];
    const float* Wo = (const float*)d_in[8];
    const float* bo = (const float*)d_in[9];
    float* out = (float*)d_out;

    __half *Qh, *Kh, *Vh, *AOh, *xh, *zh;
    __half *Wqh, *Wkh, *Wvh, *Woh;
    float* Part;
    cudaGetSymbolAddress((void**)&Qh,  g_Qh);
    cudaGetSymbolAddress((void**)&Kh,  g_Kh);
    cudaGetSymbolAddress((void**)&Vh,  g_Vh);
    cudaGetSymbolAddress((void**)&AOh, g_AOh);
    cudaGetSymbolAddress((void**)&Part, g_part);
    cudaGetSymbolAddress((void**)&xh,  g_xh);
    cudaGetSymbolAddress((void**)&zh,  g_zh);
    cudaGetSymbolAddress((void**)&Wqh, g_Wqh);
    cudaGetSymbolAddress((void**)&Wkh, g_Wkh);
    cudaGetSymbolAddress((void**)&Wvh, g_Wvh);
    cudaGetSymbolAddress((void**)&Woh, g_Woh);

    static cudaStream_t s1 = nullptr, s2 = nullptr, s3 = nullptr;
    static cudaEvent_t ev0, evz, evx, evq, evk, evv;
    if (!s1) {
        cudaStreamCreateWithFlags(&s1, cudaStreamNonBlocking);
        cudaStreamCreateWithFlags(&s2, cudaStreamNonBlocking);
        cudaStreamCreateWithFlags(&s3, cudaStreamNonBlocking);
        cudaEventCreateWithFlags(&ev0, cudaEventDisableTiming);
        cudaEventCreateWithFlags(&evz, cudaEventDisableTiming);
        cudaEventCreateWithFlags(&evx, cudaEventDisableTiming);
        cudaEventCreateWithFlags(&evq, cudaEventDisableTiming);
        cudaEventCreateWithFlags(&evk, cudaEventDisableTiming);
        cudaEventCreateWithFlags(&evv, cudaEventDisableTiming);
        cudaFuncSetAttribute(gemm_mma6_kernel,
                             cudaFuncAttributeMaxDynamicSharedMemorySize, GSMEM);
    }

    // Fork side streams from the origin stream.
    cudaEventRecord(ev0, 0);
    cudaStreamWaitEvent(s1, ev0, 0);
    cudaStreamWaitEvent(s2, ev0, 0);
    cudaStreamWaitEvent(s3, ev0, 0);

    // s0: activation rounding (+Wo rounding, overlapped by side streams)
    conv_round_kernel<<<32, 256>>>((const float4*)z, (uint2*)zh, 32768);
    cudaEventRecord(evz, 0);
    conv_round_kernel<<<64, 256>>>((const float4*)x, (uint2*)xh, 65536);
    cudaEventRecord(evx, 0);
    conv_round_kernel<<<4096, 256>>>((const float4*)Wo, (uint2*)Woh, 4194304);

    // grid: (M tiles, N tiles) — M fastest so waves share B via L2
    dim3 gQKV(TOK / 128, DTOT / 256, 1);

    // s1: Wq conversion + Q projection (fp16)
    conv_round_kernel<<<2048, 256, 0, s1>>>((const float4*)Wq, (uint2*)Wqh, 2097152);
    cudaStreamWaitEvent(s1, evz, 0);
    gemm_mma6_kernel<<<gQKV, 512, GSMEM, s1>>>(zh, 256, Wqh, DTOT, bq, 2,
                                               nullptr, Qh, DTOT, 0, 256);
    cudaEventRecord(evq, s1);

    // s2: Wk conversion + K projection
    conv_round_kernel<<<4096, 256, 0, s2>>>((const float4*)Wk, (uint2*)Wkh, 4194304);
    cudaStreamWaitEvent(s2, evx, 0);
    gemm_mma6_kernel<<<gQKV, 512, GSMEM, s2>>>(xh, 512, Wkh, DTOT, bk, 2,
                                               nullptr, Kh, DTOT, 0, 512);
    cudaEventRecord(evk, s2);

    // s3: Wv conversion + V projection
    conv_round_kernel<<<4096, 256, 0, s3>>>((const float4*)Wv, (uint2*)Wvh, 4194304);
    cudaStreamWaitEvent(s3, evx, 0);
    gemm_mma6_kernel<<<gQKV, 512, GSMEM, s3>>>(xh, 512, Wvh, DTOT, bv, 2,
                                               nullptr, Vh, DTOT, 0, 512);
    cudaEventRecord(evv, s3);

    // join back to s0
    cudaStreamWaitEvent(0, evq, 0);
    cudaStreamWaitEvent(0, evk, 0);
    cudaStreamWaitEvent(0, evv, 0);

    // Attention: 4096 heads; writes AO fp16
    attn_mma_kernel<<<4096, 128>>>(Qh, Kh, Vh, AOh);

    // Output projection: split-K partials (single wave: 4x2x16 = 128 CTAs)
    dim3 gO(512 / 128, 512 / 256, NSPLIT);
    gemm_mma6_kernel<<<gO, 512, GSMEM>>>(AOh, DTOT, Woh, 512, nullptr, 0,
                                         Part, nullptr, 512,
                                         (size_t)512 * 512, DTOT / NSPLIT);

    reduce_out_kernel<<<256, 256>>>((const float4*)Part, (const float4*)bo,
                                    (float4*)out);
}